// round 8
// baseline (speedup 1.0000x reference)
#include <cuda_runtime.h>
#include <cuda_fp16.h>
#include <math.h>
#include <stdint.h>

#define HDIM   256
#define F0DIM  512
#define CDIM   64
#define MAXN   50000
#define MAXE   800000

// -------- static device scratch (no allocations allowed) --------
__device__ float g_Aa[(size_t)MAXN * HDIM];
__device__ float g_Ab[(size_t)MAXN * HDIM];

__device__ __align__(256) __half g_X0hi[(size_t)MAXN * F0DIM];
__device__ __align__(256) __half g_X0lo[(size_t)MAXN * F0DIM];
__device__ __align__(256) __half g_X1hi[(size_t)MAXN * F0DIM];
__device__ __align__(256) __half g_X1lo[(size_t)MAXN * F0DIM];
__device__ __align__(256) __half g_Hahi[(size_t)MAXN * HDIM];
__device__ __align__(256) __half g_Halo[(size_t)MAXN * HDIM];
__device__ __align__(256) __half g_Hbhi[(size_t)MAXN * HDIM];
__device__ __align__(256) __half g_Hblo[(size_t)MAXN * HDIM];
__device__ __align__(256) __half g_CAThi[(size_t)MAXN * 2 * HDIM];
__device__ __align__(256) __half g_CATlo[(size_t)MAXN * 2 * HDIM];
__device__ __align__(256) __half g_Whi[557056];
__device__ __align__(256) __half g_Wlo[557056];

__device__ int   g_counts[MAXN];
__device__ int   g_cursor[MAXN];
__device__ int   g_rowptr[MAXN + 1];
__device__ int   g_csr_src[MAXE];
__device__ float g_csr_w[MAXE];

// weight plane offsets
#define OFF_W1a 0
#define OFF_W2a 131072
#define OFF_LWa 196608
#define OFF_W1b 262144
#define OFF_W2b 393216
#define OFF_LWb 458752
#define OFF_LW  524288

// ============================================================================
// fp32 -> (hi, lo) half planes, 4 elems/thread
// ============================================================================
__global__ void split_kernel(const float* __restrict__ in,
                             __half* __restrict__ hi, __half* __restrict__ lo, int n4)
{
    int i = blockIdx.x * blockDim.x + threadIdx.x;
    if (i >= n4) return;
    float4 v = __ldg(((const float4*)in) + i);
    float f[4] = { v.x, v.y, v.z, v.w };
    __half h[4], l[4];
#pragma unroll
    for (int j = 0; j < 4; j++) {
        h[j] = __float2half_rn(f[j]);
        l[j] = __float2half_rn(f[j] - __half2float(h[j]));
    }
    *(uint2*)(hi + 4 * (size_t)i) = *(uint2*)h;
    *(uint2*)(lo + 4 * (size_t)i) = *(uint2*)l;
}

// ============================================================================
// fp16 TC GEMM, pre-split hi/lo planes, 512 threads (16 warps, 4x4 grid),
// 128x128x32 tile, warp tile 32x32, double-buffered SMEM.
// ============================================================================
#define BM 128
#define BN 128
#define BKK 32
#define NK2 16
#define SA2 136
#define SB2 136
#define APLANE (NK2 * SA2)
#define BPLANE (NK2 * SB2)
#define BUF_H2 (2 * APLANE + 2 * BPLANE)
#define SMEM_BYTES (2 * BUF_H2 * 4)

__device__ __forceinline__ void mma_f16(float c[4], const uint32_t a[4], const uint32_t b[2]) {
    asm volatile(
        "mma.sync.aligned.m16n8k16.row.col.f32.f16.f16.f32 "
        "{%0,%1,%2,%3}, {%4,%5,%6,%7}, {%8,%9}, {%0,%1,%2,%3};"
        : "+f"(c[0]), "+f"(c[1]), "+f"(c[2]), "+f"(c[3])
        : "r"(a[0]), "r"(a[1]), "r"(a[2]), "r"(a[3]), "r"(b[0]), "r"(b[1]));
}

__global__ void __launch_bounds__(512)
hgemm_kernel(const __half* __restrict__ Ahi, const __half* __restrict__ Alo,
             const __half* __restrict__ Bhi, const __half* __restrict__ Blo,
             const float* __restrict__ bias, float* __restrict__ C,
             int M, int N, int K)
{
    extern __shared__ __half2 sm[];

    const int tid  = threadIdx.x;
    const int warp = tid >> 5;            // 0..15
    const int lane = tid & 31;
    const int g    = lane >> 2;
    const int tig  = lane & 3;
    const int mBase = (warp & 3) * 32;    // 4 warps along M
    const int nBase = (warp >> 2) * 32;   // 4 warps along N
    const int rowBase = blockIdx.y * BM;
    const int colBase = blockIdx.x * BN;

    float acc[2][4][4];
#pragma unroll
    for (int i = 0; i < 2; i++)
#pragma unroll
        for (int j = 0; j < 4; j++)
#pragma unroll
            for (int r = 0; r < 4; r++) acc[i][j][r] = 0.f;

    // A-load: tid -> row (tid&127), chunk sel (tid>>7 in 0..3), 8 halves each plane
    const int ar  = tid & 127;
    const int sel = tid >> 7;             // halves offset sel*8
    // B-load: warp -> k2 row (0..15); lane -> 4 cols at 4*lane
    const int bc  = 4 * lane;

    uint4 paH, paL;
    uint2 pb[4];  // [Bhi even, Bhi odd, Blo even, Blo odd]

    auto loadG = [&](int k0) {
        const int grow = rowBase + ar;
        if (grow < M) {
            paH = *(const uint4*)(Ahi + (size_t)grow * K + k0 + sel * 8);
            paL = *(const uint4*)(Alo + (size_t)grow * K + k0 + sel * 8);
        } else {
            paH = make_uint4(0u, 0u, 0u, 0u);
            paL = make_uint4(0u, 0u, 0u, 0u);
        }
        const int kk  = k0 + 2 * warp;
        const int col = colBase + bc;
        if (col < N) {
            const __half* q = Bhi + (size_t)kk * N + col;
            const __half* r = Blo + (size_t)kk * N + col;
            pb[0] = *(const uint2*)q;       pb[1] = *(const uint2*)(q + N);
            pb[2] = *(const uint2*)r;       pb[3] = *(const uint2*)(r + N);
        } else {
            uint2 z = make_uint2(0u, 0u);
            pb[0] = z; pb[1] = z; pb[2] = z; pb[3] = z;
        }
    };

    auto storeS = [&](int buf) {
        __half2* sA_hi = sm + (size_t)buf * BUF_H2;
        __half2* sA_lo = sA_hi + APLANE;
        __half2* sB_hi = sA_lo + APLANE;
        __half2* sB_lo = sB_hi + BPLANE;
        {
            const uint32_t uH[4] = { paH.x, paH.y, paH.z, paH.w };
            const uint32_t uL[4] = { paL.x, paL.y, paL.z, paL.w };
#pragma unroll
            for (int q = 0; q < 4; q++) {
                sA_hi[(sel * 4 + q) * SA2 + ar] = *(const __half2*)&uH[q];
                sA_lo[(sel * 4 + q) * SA2 + ar] = *(const __half2*)&uL[q];
            }
        }
        {
            // interleave (k even, k odd) into half2 per column, store uint4
            uint4 sh, sl;
            sh.x = __byte_perm(pb[0].x, pb[1].x, 0x5410);
            sh.y = __byte_perm(pb[0].x, pb[1].x, 0x7632);
            sh.z = __byte_perm(pb[0].y, pb[1].y, 0x5410);
            sh.w = __byte_perm(pb[0].y, pb[1].y, 0x7632);
            sl.x = __byte_perm(pb[2].x, pb[3].x, 0x5410);
            sl.y = __byte_perm(pb[2].x, pb[3].x, 0x7632);
            sl.z = __byte_perm(pb[2].y, pb[3].y, 0x5410);
            sl.w = __byte_perm(pb[2].y, pb[3].y, 0x7632);
            *(uint4*)&sB_hi[warp * SB2 + bc] = sh;
            *(uint4*)&sB_lo[warp * SB2 + bc] = sl;
        }
    };

    const int nIter = K / BKK;
    loadG(0);
    storeS(0);
    __syncthreads();
    if (nIter > 1) loadG(BKK);

    for (int it = 0; it < nIter; it++) {
        const __half2* sA_hi = sm + (size_t)(it & 1) * BUF_H2;
        const __half2* sA_lo = sA_hi + APLANE;
        const __half2* sB_hi = sA_lo + APLANE;
        const __half2* sB_lo = sB_hi + BPLANE;

#pragma unroll
        for (int ks = 0; ks < 2; ks++) {
            const int k2a = ks * 8 + tig;
            const int k2b = k2a + 4;

            uint32_t ahi[2][4], alo[2][4];
#pragma unroll
            for (int mi = 0; mi < 2; mi++) {
                const int m0 = mBase + mi * 16 + g;
                ahi[mi][0] = *(const uint32_t*)&sA_hi[k2a * SA2 + m0];
                ahi[mi][1] = *(const uint32_t*)&sA_hi[k2a * SA2 + m0 + 8];
                ahi[mi][2] = *(const uint32_t*)&sA_hi[k2b * SA2 + m0];
                ahi[mi][3] = *(const uint32_t*)&sA_hi[k2b * SA2 + m0 + 8];
                alo[mi][0] = *(const uint32_t*)&sA_lo[k2a * SA2 + m0];
                alo[mi][1] = *(const uint32_t*)&sA_lo[k2a * SA2 + m0 + 8];
                alo[mi][2] = *(const uint32_t*)&sA_lo[k2b * SA2 + m0];
                alo[mi][3] = *(const uint32_t*)&sA_lo[k2b * SA2 + m0 + 8];
            }
            uint32_t bhi[4][2], blo[4][2];
#pragma unroll
            for (int ni = 0; ni < 4; ni++) {
                const int n0 = nBase + ni * 8 + g;
                bhi[ni][0] = *(const uint32_t*)&sB_hi[k2a * SB2 + n0];
                bhi[ni][1] = *(const uint32_t*)&sB_hi[k2b * SB2 + n0];
                blo[ni][0] = *(const uint32_t*)&sB_lo[k2a * SB2 + n0];
                blo[ni][1] = *(const uint32_t*)&sB_lo[k2b * SB2 + n0];
            }
#pragma unroll
            for (int mi = 0; mi < 2; mi++)
#pragma unroll
                for (int ni = 0; ni < 4; ni++)
                    mma_f16(acc[mi][ni], alo[mi], bhi[ni]);
#pragma unroll
            for (int mi = 0; mi < 2; mi++)
#pragma unroll
                for (int ni = 0; ni < 4; ni++)
                    mma_f16(acc[mi][ni], ahi[mi], blo[ni]);
#pragma unroll
            for (int mi = 0; mi < 2; mi++)
#pragma unroll
                for (int ni = 0; ni < 4; ni++)
                    mma_f16(acc[mi][ni], ahi[mi], bhi[ni]);
        }

        if (it + 1 < nIter) storeS((it + 1) & 1);
        __syncthreads();
        if (it + 2 < nIter) loadG((it + 2) * BKK);
    }

    // epilogue
#pragma unroll
    for (int mi = 0; mi < 2; mi++) {
#pragma unroll
        for (int ni = 0; ni < 4; ni++) {
            const int col = colBase + nBase + ni * 8 + 2 * tig;
            if (col >= N) continue;
            float bx = 0.f, by = 0.f;
            if (bias) { bx = __ldg(&bias[col]); by = __ldg(&bias[col + 1]); }
            const int row0 = rowBase + mBase + mi * 16 + g;
            const int row1 = row0 + 8;
            if (row0 < M) {
                float2 v = make_float2(acc[mi][ni][0] + bx, acc[mi][ni][1] + by);
                *(float2*)(C + (size_t)row0 * N + col) = v;
            }
            if (row1 < M) {
                float2 v = make_float2(acc[mi][ni][2] + bx, acc[mi][ni][3] + by);
                *(float2*)(C + (size_t)row1 * N + col) = v;
            }
        }
    }
}

// ============================================================================
// CSR build: histogram -> scan -> scatter
// ============================================================================
__global__ void count_kernel(const int* __restrict__ dst, int* __restrict__ counts, int E)
{
    int e = blockIdx.x * blockDim.x + threadIdx.x;
    if (e < E) atomicAdd(&counts[dst[e]], 1);
}

__global__ void __launch_bounds__(1024)
scan_kernel(const int* __restrict__ counts, int* __restrict__ rowptr, int n)
{
    __shared__ int sm[1024];
    __shared__ int carry_s;
    int tid = threadIdx.x;
    if (tid == 0) carry_s = 0;
    __syncthreads();
    for (int base = 0; base < n; base += 1024) {
        int v = (base + tid < n) ? counts[base + tid] : 0;
        sm[tid] = v;
        __syncthreads();
#pragma unroll
        for (int off = 1; off < 1024; off <<= 1) {
            int t = (tid >= off) ? sm[tid - off] : 0;
            __syncthreads();
            sm[tid] += t;
            __syncthreads();
        }
        int carry = carry_s;
        if (base + tid < n) rowptr[base + tid] = carry + sm[tid] - v;
        __syncthreads();
        if (tid == 1023) carry_s = carry + sm[1023];
        __syncthreads();
    }
    if (tid == 0) rowptr[n] = carry_s;
}

__global__ void scatter_kernel(const int* __restrict__ src, const int* __restrict__ dst,
                               const float* __restrict__ w,
                               const int* __restrict__ rowptr, int* __restrict__ cursor,
                               int* __restrict__ csr_src, float* __restrict__ csr_w, int E)
{
    int e = blockIdx.x * blockDim.x + threadIdx.x;
    if (e >= E) return;
    int d = dst[e];
    int pos = rowptr[d] + atomicAdd(&cursor[d], 1);
    csr_src[pos] = src[e];
    csr_w[pos]   = w[e];
}

// ============================================================================
// Gather SpMM, dual branch, bias(+relu) fused, 4-edge unrolled (MLP),
// emits hi/lo half planes.
// ============================================================================
__global__ void __launch_bounds__(256)
spmm_csr_dual_kernel(const int* __restrict__ rowptr,
                     const int* __restrict__ csr_src, const float* __restrict__ csr_w,
                     const float* __restrict__ ha, const float* __restrict__ hb,
                     __half* __restrict__ oa_hi, __half* __restrict__ oa_lo,
                     __half* __restrict__ ob_hi, __half* __restrict__ ob_lo,
                     const float* __restrict__ bias_a, const float* __restrict__ bias_b,
                     int Nn, int do_relu)
{
    int node = blockIdx.x * 4 + (threadIdx.x >> 6);
    int c    = threadIdx.x & 63;
    if (node >= Nn) return;

    const float4* ha4 = (const float4*)ha;
    const float4* hb4 = (const float4*)hb;

    float4 acca = make_float4(0.f, 0.f, 0.f, 0.f);
    float4 accb = make_float4(0.f, 0.f, 0.f, 0.f);

    const int beg = __ldg(&rowptr[node]);
    const int end = __ldg(&rowptr[node + 1]);
    int i = beg;

#define ACC_EDGE(va, vb, wv)                                            \
    do {                                                                \
        acca.x = fmaf(wv, va.x, acca.x); acca.y = fmaf(wv, va.y, acca.y);\
        acca.z = fmaf(wv, va.z, acca.z); acca.w = fmaf(wv, va.w, acca.w);\
        accb.x = fmaf(wv, vb.x, accb.x); accb.y = fmaf(wv, vb.y, accb.y);\
        accb.z = fmaf(wv, vb.z, accb.z); accb.w = fmaf(wv, vb.w, accb.w);\
    } while (0)

    for (; i + 4 <= end; i += 4) {
        int   s0 = __ldg(&csr_src[i]),     s1 = __ldg(&csr_src[i + 1]);
        int   s2 = __ldg(&csr_src[i + 2]), s3 = __ldg(&csr_src[i + 3]);
        float w0 = __ldg(&csr_w[i]),       w1 = __ldg(&csr_w[i + 1]);
        float w2 = __ldg(&csr_w[i + 2]),   w3 = __ldg(&csr_w[i + 3]);
        float4 va0 = __ldg(&ha4[(size_t)s0 * 64 + c]);
        float4 va1 = __ldg(&ha4[(size_t)s1 * 64 + c]);
        float4 va2 = __ldg(&ha4[(size_t)s2 * 64 + c]);
        float4 va3 = __ldg(&ha4[(size_t)s3 * 64 + c]);
        float4 vb0 = __ldg(&hb4[(size_t)s0 * 64 + c]);
        float4 vb1 = __ldg(&hb4[(size_t)s1 * 64 + c]);
        float4 vb2 = __ldg(&hb4[(size_t)s2 * 64 + c]);
        float4 vb3 = __ldg(&hb4[(size_t)s3 * 64 + c]);
        ACC_EDGE(va0, vb0, w0);
        ACC_EDGE(va1, vb1, w1);
        ACC_EDGE(va2, vb2, w2);
        ACC_EDGE(va3, vb3, w3);
    }
    for (; i < end; i++) {
        int   s = __ldg(&csr_src[i]);
        float w = __ldg(&csr_w[i]);
        float4 va = __ldg(&ha4[(size_t)s * 64 + c]);
        float4 vb = __ldg(&hb4[(size_t)s * 64 + c]);
        ACC_EDGE(va, vb, w);
    }
#undef ACC_EDGE

    float4 ba = __ldg(&((const float4*)bias_a)[c]);
    float4 bb = __ldg(&((const float4*)bias_b)[c]);
    acca.x += ba.x; acca.y += ba.y; acca.z += ba.z; acca.w += ba.w;
    accb.x += bb.x; accb.y += bb.y; accb.z += bb.z; accb.w += bb.w;
    if (do_relu) {
        acca.x = fmaxf(acca.x, 0.f); acca.y = fmaxf(acca.y, 0.f);
        acca.z = fmaxf(acca.z, 0.f); acca.w = fmaxf(acca.w, 0.f);
        accb.x = fmaxf(accb.x, 0.f); accb.y = fmaxf(accb.y, 0.f);
        accb.z = fmaxf(accb.z, 0.f); accb.w = fmaxf(accb.w, 0.f);
    }

    const size_t off = (size_t)node * HDIM + 4 * c;
    float fa[4] = { acca.x, acca.y, acca.z, acca.w };
    float fb[4] = { accb.x, accb.y, accb.z, accb.w };
    __half hah[4], hal[4], hbh[4], hbl[4];
#pragma unroll
    for (int j = 0; j < 4; j++) {
        hah[j] = __float2half_rn(fa[j]);
        hal[j] = __float2half_rn(fa[j] - __half2float(hah[j]));
        hbh[j] = __float2half_rn(fb[j]);
        hbl[j] = __float2half_rn(fb[j] - __half2float(hbh[j]));
    }
    *(uint2*)(oa_hi + off) = *(uint2*)hah;
    *(uint2*)(oa_lo + off) = *(uint2*)hal;
    *(uint2*)(ob_hi + off) = *(uint2*)hbh;
    *(uint2*)(ob_lo + off) = *(uint2*)hbl;
}

// ============================================================================
// log_softmax variants (one warp per row)
// ============================================================================
__global__ void logsoftmax_split_kernel(const float* __restrict__ in,
                                        __half* __restrict__ out_hi,
                                        __half* __restrict__ out_lo,
                                        int nrows, int out_stride)
{
    const int L = HDIM;
    int row  = blockIdx.x * (blockDim.x >> 5) + (threadIdx.x >> 5);
    int lane = threadIdx.x & 31;
    if (row >= nrows) return;
    const float* r = in + (size_t)row * L;
    float vals[L / 32];
    float m = -3.4e38f;
#pragma unroll
    for (int t = 0; t < L / 32; t++) {
        vals[t] = r[lane + t * 32];
        m = fmaxf(m, vals[t]);
    }
#pragma unroll
    for (int o = 16; o; o >>= 1) m = fmaxf(m, __shfl_xor_sync(0xffffffffu, m, o));
    float s = 0.f;
#pragma unroll
    for (int t = 0; t < L / 32; t++) s += expf(vals[t] - m);
#pragma unroll
    for (int o = 16; o; o >>= 1) s += __shfl_xor_sync(0xffffffffu, s, o);
    float lse = m + logf(s);
    size_t base = (size_t)row * out_stride;
#pragma unroll
    for (int t = 0; t < L / 32; t++) {
        float v = vals[t] - lse;
        __half h = __float2half_rn(v);
        out_hi[base + lane + t * 32] = h;
        out_lo[base + lane + t * 32] = __float2half_rn(v - __half2float(h));
    }
}

template <int L>
__global__ void logsoftmax_kernel(const float* __restrict__ in, float* __restrict__ out,
                                  int nrows, int out_stride)
{
    int row  = blockIdx.x * (blockDim.x >> 5) + (threadIdx.x >> 5);
    int lane = threadIdx.x & 31;
    if (row >= nrows) return;
    const float* r = in + (size_t)row * L;
    float vals[L / 32];
    float m = -3.4e38f;
#pragma unroll
    for (int t = 0; t < L / 32; t++) {
        vals[t] = r[lane + t * 32];
        m = fmaxf(m, vals[t]);
    }
#pragma unroll
    for (int o = 16; o; o >>= 1) m = fmaxf(m, __shfl_xor_sync(0xffffffffu, m, o));
    float s = 0.f;
#pragma unroll
    for (int t = 0; t < L / 32; t++) s += expf(vals[t] - m);
#pragma unroll
    for (int o = 16; o; o >>= 1) s += __shfl_xor_sync(0xffffffffu, s, o);
    float lse = m + logf(s);
    float* wptr = out + (size_t)row * out_stride;
#pragma unroll
    for (int t = 0; t < L / 32; t++) wptr[lane + t * 32] = vals[t] - lse;
}

// ============================================================================
// host side
// ============================================================================
static void hgemm(const __half* Ahi, const __half* Alo,
                  const __half* Bhi, const __half* Blo,
                  const float* bias, float* C, int M, int N, int K)
{
    dim3 grid((N + BN - 1) / BN, (M + BM - 1) / BM);
    hgemm_kernel<<<grid, 512, SMEM_BYTES>>>(Ahi, Alo, Bhi, Blo, bias, C, M, N, K);
}

static void split(const float* in, __half* hi, __half* lo, int n)
{
    int n4 = n / 4;
    split_kernel<<<(n4 + 255) / 256, 256>>>(in, hi, lo, n4);
}

extern "C" void kernel_launch(void* const* d_in, const int* in_sizes, int n_in,
                              void* d_out, int out_size)
{
    const float* x0   = (const float*)d_in[0];
    const float* x1   = (const float*)d_in[1];
    const int*   esrc = (const int*)d_in[2];
    const int*   edst = (const int*)d_in[3];
    const float* ew   = (const float*)d_in[4];
    const float* W1a = (const float*)d_in[5];  const float* b1a = (const float*)d_in[6];
    const float* W2a = (const float*)d_in[7];  const float* b2a = (const float*)d_in[8];
    const float* LWa = (const float*)d_in[9];  const float* Lba = (const float*)d_in[10];
    const float* W1b = (const float*)d_in[11]; const float* b1b = (const float*)d_in[12];
    const float* W2b = (const float*)d_in[13]; const float* b2b = (const float*)d_in[14];
    const float* LWb = (const float*)d_in[15]; const float* Lbb = (const float*)d_in[16];
    const float* LW  = (const float*)d_in[17]; const float* Lb  = (const float*)d_in[18];

    const int Nn = in_sizes[0] / F0DIM;
    const int E  = in_sizes[2];

    cudaFuncSetAttribute(hgemm_kernel,
                         cudaFuncAttributeMaxDynamicSharedMemorySize, SMEM_BYTES);

    float *Aa, *Ab;
    cudaGetSymbolAddress((void**)&Aa, g_Aa);
    cudaGetSymbolAddress((void**)&Ab, g_Ab);
    __half *X0hi, *X0lo, *X1hi, *X1lo, *Hahi, *Halo, *Hbhi, *Hblo, *CAThi, *CATlo, *Whi, *Wlo;
    cudaGetSymbolAddress((void**)&X0hi, g_X0hi);  cudaGetSymbolAddress((void**)&X0lo, g_X0lo);
    cudaGetSymbolAddress((void**)&X1hi, g_X1hi);  cudaGetSymbolAddress((void**)&X1lo, g_X1lo);
    cudaGetSymbolAddress((void**)&Hahi, g_Hahi);  cudaGetSymbolAddress((void**)&Halo, g_Halo);
    cudaGetSymbolAddress((void**)&Hbhi, g_Hbhi);  cudaGetSymbolAddress((void**)&Hblo, g_Hblo);
    cudaGetSymbolAddress((void**)&CAThi, g_CAThi); cudaGetSymbolAddress((void**)&CATlo, g_CATlo);
    cudaGetSymbolAddress((void**)&Whi, g_Whi);    cudaGetSymbolAddress((void**)&Wlo, g_Wlo);

    int *counts, *cursor, *rowptr, *csr_src;
    float *csr_w;
    cudaGetSymbolAddress((void**)&counts,  g_counts);
    cudaGetSymbolAddress((void**)&cursor,  g_cursor);
    cudaGetSymbolAddress((void**)&rowptr,  g_rowptr);
    cudaGetSymbolAddress((void**)&csr_src, g_csr_src);
    cudaGetSymbolAddress((void**)&csr_w,   g_csr_w);

    // ---- split inputs & weights to half planes ----
    split(x0, X0hi, X0lo, Nn * F0DIM);
    split(x1, X1hi, X1lo, Nn * F0DIM);
    split(W1a, Whi + OFF_W1a, Wlo + OFF_W1a, F0DIM * HDIM);
    split(W2a, Whi + OFF_W2a, Wlo + OFF_W2a, HDIM * HDIM);
    split(LWa, Whi + OFF_LWa, Wlo + OFF_LWa, HDIM * HDIM);
    split(W1b, Whi + OFF_W1b, Wlo + OFF_W1b, F0DIM * HDIM);
    split(W2b, Whi + OFF_W2b, Wlo + OFF_W2b, HDIM * HDIM);
    split(LWb, Whi + OFF_LWb, Wlo + OFF_LWb, HDIM * HDIM);
    split(LW,  Whi + OFF_LW,  Wlo + OFF_LW,  2 * HDIM * CDIM);

    // ---- build CSR by dst ----
    cudaMemsetAsync(counts, 0, Nn * sizeof(int), 0);
    cudaMemsetAsync(cursor, 0, Nn * sizeof(int), 0);
    count_kernel<<<(E + 255) / 256, 256>>>(edst, counts, E);
    scan_kernel<<<1, 1024>>>(counts, rowptr, Nn);
    scatter_kernel<<<(E + 255) / 256, 256>>>(esrc, edst, ew, rowptr, cursor,
                                             csr_src, csr_w, E);

    const int spmmGrid = (Nn + 3) / 4;

    // ---- layer 1 ----
    hgemm(X0hi, X0lo, Whi + OFF_W1a, Wlo + OFF_W1a, nullptr, Aa, Nn, HDIM, F0DIM);
    hgemm(X1hi, X1lo, Whi + OFF_W1b, Wlo + OFF_W1b, nullptr, Ab, Nn, HDIM, F0DIM);
    spmm_csr_dual_kernel<<<spmmGrid, 256>>>(rowptr, csr_src, csr_w, Aa, Ab,
                                            Hahi, Halo, Hbhi, Hblo, b1a, b1b, Nn, 1);
    // ---- layer 2 ----
    hgemm(Hahi, Halo, Whi + OFF_W2a, Wlo + OFF_W2a, nullptr, Aa, Nn, HDIM, HDIM);
    hgemm(Hbhi, Hblo, Whi + OFF_W2b, Wlo + OFF_W2b, nullptr, Ab, Nn, HDIM, HDIM);
    spmm_csr_dual_kernel<<<spmmGrid, 256>>>(rowptr, csr_src, csr_w, Aa, Ab,
                                            Hahi, Halo, Hbhi, Hblo, b2a, b2b, Nn, 0);
    // ---- branch heads: linear + log_softmax into CAT planes ----
    hgemm(Hahi, Halo, Whi + OFF_LWa, Wlo + OFF_LWa, Lba, Aa, Nn, HDIM, HDIM);
    hgemm(Hbhi, Hblo, Whi + OFF_LWb, Wlo + OFF_LWb, Lbb, Ab, Nn, HDIM, HDIM);
    logsoftmax_split_kernel<<<(Nn + 7) / 8, 256>>>(Aa, CAThi,        CATlo,        Nn, 2 * HDIM);
    logsoftmax_split_kernel<<<(Nn + 7) / 8, 256>>>(Ab, CAThi + HDIM, CATlo + HDIM, Nn, 2 * HDIM);

    // ---- final: out = log_softmax(CAT @ LW + Lb) ----
    hgemm(CAThi, CATlo, Whi + OFF_LW, Wlo + OFF_LW, Lb, Aa, Nn, CDIM, 2 * HDIM);
    logsoftmax_kernel<CDIM><<<(Nn + 7) / 8, 256>>>(Aa, (float*)d_out, Nn, CDIM);
}

// round 9
// speedup vs baseline: 1.0895x; 1.0895x over previous
#include <cuda_runtime.h>
#include <cuda_fp16.h>
#include <math.h>
#include <stdint.h>

#define HDIM   256
#define F0DIM  512
#define CDIM   64
#define MAXN   50000
#define MAXE   800000

// -------- static device scratch (no allocations allowed) --------
__device__ float g_Aa[(size_t)MAXN * HDIM];
__device__ float g_Ab[(size_t)MAXN * HDIM];

__device__ __align__(256) __half g_X0hi[(size_t)MAXN * F0DIM];
__device__ __align__(256) __half g_X0lo[(size_t)MAXN * F0DIM];
__device__ __align__(256) __half g_X1hi[(size_t)MAXN * F0DIM];
__device__ __align__(256) __half g_X1lo[(size_t)MAXN * F0DIM];
__device__ __align__(256) __half g_Hahi[(size_t)MAXN * HDIM];
__device__ __align__(256) __half g_Halo[(size_t)MAXN * HDIM];
__device__ __align__(256) __half g_Hbhi[(size_t)MAXN * HDIM];
__device__ __align__(256) __half g_Hblo[(size_t)MAXN * HDIM];
__device__ __align__(256) __half g_CAThi[(size_t)MAXN * 2 * HDIM];
__device__ __align__(256) __half g_CATlo[(size_t)MAXN * 2 * HDIM];
__device__ __align__(256) __half g_Whi[557056];
__device__ __align__(256) __half g_Wlo[557056];

__device__ int   g_counts[MAXN];
__device__ int   g_cursor[MAXN];
__device__ int   g_rowptr[MAXN + 1];
__device__ int   g_csr_src[MAXE];
__device__ float g_csr_w[MAXE];

// weight plane offsets
#define OFF_W1a 0
#define OFF_W2a 131072
#define OFF_LWa 196608
#define OFF_W1b 262144
#define OFF_W2b 393216
#define OFF_LWb 458752
#define OFF_LW  524288

// ============================================================================
// fp32 -> (hi, lo) half planes, 4 elems/thread
// ============================================================================
__global__ void split_kernel(const float* __restrict__ in,
                             __half* __restrict__ hi, __half* __restrict__ lo, int n4)
{
    int i = blockIdx.x * blockDim.x + threadIdx.x;
    if (i >= n4) return;
    float4 v = __ldg(((const float4*)in) + i);
    float f[4] = { v.x, v.y, v.z, v.w };
    __half h[4], l[4];
#pragma unroll
    for (int j = 0; j < 4; j++) {
        h[j] = __float2half_rn(f[j]);
        l[j] = __float2half_rn(f[j] - __half2float(h[j]));
    }
    *(uint2*)(hi + 4 * (size_t)i) = *(uint2*)h;
    *(uint2*)(lo + 4 * (size_t)i) = *(uint2*)l;
}

// ============================================================================
// fp16 TC GEMM (R7 config: 256 thr, 8 warps 2x4, warp tile 64x32),
// pre-split hi/lo planes, 128x128x32 tile, double-buffered SMEM.
// Dual variant: blockIdx.z selects branch {A set, B set} (batched launches).
// ============================================================================
#define BM 128
#define BN 128
#define BKK 32
#define NK2 16
#define SA2 136
#define SB2 136
#define APLANE (NK2 * SA2)
#define BPLANE (NK2 * SB2)
#define BUF_H2 (2 * APLANE + 2 * BPLANE)
#define SMEM_BYTES (2 * BUF_H2 * 4)

__device__ __forceinline__ void mma_f16(float c[4], const uint32_t a[4], const uint32_t b[2]) {
    asm volatile(
        "mma.sync.aligned.m16n8k16.row.col.f32.f16.f16.f32 "
        "{%0,%1,%2,%3}, {%4,%5,%6,%7}, {%8,%9}, {%0,%1,%2,%3};"
        : "+f"(c[0]), "+f"(c[1]), "+f"(c[2]), "+f"(c[3])
        : "r"(a[0]), "r"(a[1]), "r"(a[2]), "r"(a[3]), "r"(b[0]), "r"(b[1]));
}

struct GemmArgs {
    const __half* Ahi; const __half* Alo;
    const __half* Bhi; const __half* Blo;
    const float*  bias; float* C;
};

__global__ void __launch_bounds__(256)
hgemm_kernel(GemmArgs a0, GemmArgs a1, int M, int N, int K)
{
    extern __shared__ __half2 sm[];

    const GemmArgs& A = blockIdx.z ? a1 : a0;
    const __half* __restrict__ Ahi = A.Ahi;
    const __half* __restrict__ Alo = A.Alo;
    const __half* __restrict__ Bhi = A.Bhi;
    const __half* __restrict__ Blo = A.Blo;
    const float*  __restrict__ bias = A.bias;
    float* __restrict__ C = A.C;

    const int tid  = threadIdx.x;
    const int warp = tid >> 5;
    const int lane = tid & 31;
    const int g    = lane >> 2;
    const int tig  = lane & 3;
    const int mBase = (warp & 1) * 64;
    const int nBase = (warp >> 1) * 32;
    const int rowBase = blockIdx.y * BM;
    const int colBase = blockIdx.x * BN;

    float acc[4][4][4];
#pragma unroll
    for (int i = 0; i < 4; i++)
#pragma unroll
        for (int j = 0; j < 4; j++)
#pragma unroll
            for (int r = 0; r < 4; r++) acc[i][j][r] = 0.f;

    const int ar   = tid & 127;
    const int ak2  = (tid >> 7) * 8;
    const int aKh  = ak2 * 2;
    const int bcol0 = 2 * lane;

    uint4    pa[4];
    uint32_t pbr[16];

    auto loadG = [&](int k0) {
        const int grow = rowBase + ar;
        if (grow < M) {
            const __half* pH = Ahi + (size_t)grow * K + k0 + aKh;
            const __half* pL = Alo + (size_t)grow * K + k0 + aKh;
            pa[0] = *(const uint4*)pH;       pa[1] = *(const uint4*)(pH + 8);
            pa[2] = *(const uint4*)pL;       pa[3] = *(const uint4*)(pL + 8);
        } else {
            uint4 z = make_uint4(0u, 0u, 0u, 0u);
            pa[0] = z; pa[1] = z; pa[2] = z; pa[3] = z;
        }
#pragma unroll
        for (int s = 0; s < 2; s++) {
            const int k2 = warp + 8 * s;
            const int kk = k0 + 2 * k2;
#pragma unroll
            for (int c = 0; c < 2; c++) {
                const int col = colBase + bcol0 + 64 * c;
                const bool ok = (col < N);
                const __half* q = Bhi + (size_t)kk * N + col;
                const __half* r = Blo + (size_t)kk * N + col;
                pbr[((0 * 2 + s) * 2 + 0) * 2 + c] = ok ? *(const uint32_t*)q       : 0u;
                pbr[((0 * 2 + s) * 2 + 1) * 2 + c] = ok ? *(const uint32_t*)(q + N) : 0u;
                pbr[((1 * 2 + s) * 2 + 0) * 2 + c] = ok ? *(const uint32_t*)r       : 0u;
                pbr[((1 * 2 + s) * 2 + 1) * 2 + c] = ok ? *(const uint32_t*)(r + N) : 0u;
            }
        }
    };

    auto storeS = [&](int buf) {
        __half2* sA_hi = sm + (size_t)buf * BUF_H2;
        __half2* sA_lo = sA_hi + APLANE;
        __half2* sB_hi = sA_lo + APLANE;
        __half2* sB_lo = sB_hi + BPLANE;
#pragma unroll
        for (int pl = 0; pl < 2; pl++) {
            __half2* dst = pl ? sA_lo : sA_hi;
#pragma unroll
            for (int j = 0; j < 2; j++) {
                uint4 v = pa[pl * 2 + j];
                const uint32_t u[4] = { v.x, v.y, v.z, v.w };
#pragma unroll
                for (int q = 0; q < 4; q++)
                    dst[(ak2 + j * 4 + q) * SA2 + ar] = *(const __half2*)&u[q];
            }
        }
#pragma unroll
        for (int pl = 0; pl < 2; pl++) {
            __half2* dst = pl ? sB_lo : sB_hi;
#pragma unroll
            for (int s = 0; s < 2; s++) {
                const int k2 = warp + 8 * s;
#pragma unroll
                for (int c = 0; c < 2; c++) {
                    uint32_t r0 = pbr[((pl * 2 + s) * 2 + 0) * 2 + c];
                    uint32_t r1 = pbr[((pl * 2 + s) * 2 + 1) * 2 + c];
                    uint2 st = make_uint2(__byte_perm(r0, r1, 0x5410),
                                          __byte_perm(r0, r1, 0x7632));
                    *(uint2*)&dst[k2 * SB2 + bcol0 + 64 * c] = st;
                }
            }
        }
    };

    const int nIter = K / BKK;
    loadG(0);
    storeS(0);
    __syncthreads();
    if (nIter > 1) loadG(BKK);

    for (int it = 0; it < nIter; it++) {
        const __half2* sA_hi = sm + (size_t)(it & 1) * BUF_H2;
        const __half2* sA_lo = sA_hi + APLANE;
        const __half2* sB_hi = sA_lo + APLANE;
        const __half2* sB_lo = sB_hi + BPLANE;

#pragma unroll
        for (int ks = 0; ks < 2; ks++) {
            const int k2a = ks * 8 + tig;
            const int k2b = k2a + 4;

            uint32_t ahi[4][4], alo[4][4];
#pragma unroll
            for (int mi = 0; mi < 4; mi++) {
                const int m0 = mBase + mi * 16 + g;
                ahi[mi][0] = *(const uint32_t*)&sA_hi[k2a * SA2 + m0];
                ahi[mi][1] = *(const uint32_t*)&sA_hi[k2a * SA2 + m0 + 8];
                ahi[mi][2] = *(const uint32_t*)&sA_hi[k2b * SA2 + m0];
                ahi[mi][3] = *(const uint32_t*)&sA_hi[k2b * SA2 + m0 + 8];
                alo[mi][0] = *(const uint32_t*)&sA_lo[k2a * SA2 + m0];
                alo[mi][1] = *(const uint32_t*)&sA_lo[k2a * SA2 + m0 + 8];
                alo[mi][2] = *(const uint32_t*)&sA_lo[k2b * SA2 + m0];
                alo[mi][3] = *(const uint32_t*)&sA_lo[k2b * SA2 + m0 + 8];
            }
            uint32_t bhi[4][2], blo[4][2];
#pragma unroll
            for (int ni = 0; ni < 4; ni++) {
                const int n0 = nBase + ni * 8 + g;
                bhi[ni][0] = *(const uint32_t*)&sB_hi[k2a * SB2 + n0];
                bhi[ni][1] = *(const uint32_t*)&sB_hi[k2b * SB2 + n0];
                blo[ni][0] = *(const uint32_t*)&sB_lo[k2a * SB2 + n0];
                blo[ni][1] = *(const uint32_t*)&sB_lo[k2b * SB2 + n0];
            }
#pragma unroll
            for (int mi = 0; mi < 4; mi++)
#pragma unroll
                for (int ni = 0; ni < 4; ni++)
                    mma_f16(acc[mi][ni], alo[mi], bhi[ni]);
#pragma unroll
            for (int mi = 0; mi < 4; mi++)
#pragma unroll
                for (int ni = 0; ni < 4; ni++)
                    mma_f16(acc[mi][ni], ahi[mi], blo[ni]);
#pragma unroll
            for (int mi = 0; mi < 4; mi++)
#pragma unroll
                for (int ni = 0; ni < 4; ni++)
                    mma_f16(acc[mi][ni], ahi[mi], bhi[ni]);
        }

        if (it + 1 < nIter) storeS((it + 1) & 1);
        __syncthreads();
        if (it + 2 < nIter) loadG((it + 2) * BKK);
    }

    // epilogue
#pragma unroll
    for (int mi = 0; mi < 4; mi++) {
#pragma unroll
        for (int ni = 0; ni < 4; ni++) {
            const int col = colBase + nBase + ni * 8 + 2 * tig;
            if (col >= N) continue;
            float bx = 0.f, by = 0.f;
            if (bias) { bx = __ldg(&bias[col]); by = __ldg(&bias[col + 1]); }
            const int row0 = rowBase + mBase + mi * 16 + g;
            const int row1 = row0 + 8;
            if (row0 < M) {
                float2 v = make_float2(acc[mi][ni][0] + bx, acc[mi][ni][1] + by);
                *(float2*)(C + (size_t)row0 * N + col) = v;
            }
            if (row1 < M) {
                float2 v = make_float2(acc[mi][ni][2] + bx, acc[mi][ni][3] + by);
                *(float2*)(C + (size_t)row1 * N + col) = v;
            }
        }
    }
}

// ============================================================================
// CSR build: histogram -> scan -> scatter
// ============================================================================
__global__ void count_kernel(const int* __restrict__ dst, int* __restrict__ counts, int E)
{
    int e = blockIdx.x * blockDim.x + threadIdx.x;
    if (e < E) atomicAdd(&counts[dst[e]], 1);
}

__global__ void __launch_bounds__(1024)
scan_kernel(const int* __restrict__ counts, int* __restrict__ rowptr, int n)
{
    __shared__ int sm[1024];
    __shared__ int carry_s;
    int tid = threadIdx.x;
    if (tid == 0) carry_s = 0;
    __syncthreads();
    for (int base = 0; base < n; base += 1024) {
        int v = (base + tid < n) ? counts[base + tid] : 0;
        sm[tid] = v;
        __syncthreads();
#pragma unroll
        for (int off = 1; off < 1024; off <<= 1) {
            int t = (tid >= off) ? sm[tid - off] : 0;
            __syncthreads();
            sm[tid] += t;
            __syncthreads();
        }
        int carry = carry_s;
        if (base + tid < n) rowptr[base + tid] = carry + sm[tid] - v;
        __syncthreads();
        if (tid == 1023) carry_s = carry + sm[1023];
        __syncthreads();
    }
    if (tid == 0) rowptr[n] = carry_s;
}

__global__ void scatter_kernel(const int* __restrict__ src, const int* __restrict__ dst,
                               const float* __restrict__ w,
                               const int* __restrict__ rowptr, int* __restrict__ cursor,
                               int* __restrict__ csr_src, float* __restrict__ csr_w, int E)
{
    int e = blockIdx.x * blockDim.x + threadIdx.x;
    if (e >= E) return;
    int d = dst[e];
    int pos = rowptr[d] + atomicAdd(&cursor[d], 1);
    csr_src[pos] = src[e];
    csr_w[pos]   = w[e];
}

// ============================================================================
// Gather SpMM, dual branch, bias(+relu) fused, 4-edge unrolled (MLP),
// emits hi/lo half planes.
// ============================================================================
__global__ void __launch_bounds__(256)
spmm_csr_dual_kernel(const int* __restrict__ rowptr,
                     const int* __restrict__ csr_src, const float* __restrict__ csr_w,
                     const float* __restrict__ ha, const float* __restrict__ hb,
                     __half* __restrict__ oa_hi, __half* __restrict__ oa_lo,
                     __half* __restrict__ ob_hi, __half* __restrict__ ob_lo,
                     const float* __restrict__ bias_a, const float* __restrict__ bias_b,
                     int Nn, int do_relu)
{
    int node = blockIdx.x * 4 + (threadIdx.x >> 6);
    int c    = threadIdx.x & 63;
    if (node >= Nn) return;

    const float4* ha4 = (const float4*)ha;
    const float4* hb4 = (const float4*)hb;

    float4 acca = make_float4(0.f, 0.f, 0.f, 0.f);
    float4 accb = make_float4(0.f, 0.f, 0.f, 0.f);

    const int beg = __ldg(&rowptr[node]);
    const int end = __ldg(&rowptr[node + 1]);
    int i = beg;

#define ACC_EDGE(va, vb, wv)                                            \
    do {                                                                \
        acca.x = fmaf(wv, va.x, acca.x); acca.y = fmaf(wv, va.y, acca.y);\
        acca.z = fmaf(wv, va.z, acca.z); acca.w = fmaf(wv, va.w, acca.w);\
        accb.x = fmaf(wv, vb.x, accb.x); accb.y = fmaf(wv, vb.y, accb.y);\
        accb.z = fmaf(wv, vb.z, accb.z); accb.w = fmaf(wv, vb.w, accb.w);\
    } while (0)

    for (; i + 4 <= end; i += 4) {
        int   s0 = __ldg(&csr_src[i]),     s1 = __ldg(&csr_src[i + 1]);
        int   s2 = __ldg(&csr_src[i + 2]), s3 = __ldg(&csr_src[i + 3]);
        float w0 = __ldg(&csr_w[i]),       w1 = __ldg(&csr_w[i + 1]);
        float w2 = __ldg(&csr_w[i + 2]),   w3 = __ldg(&csr_w[i + 3]);
        float4 va0 = __ldg(&ha4[(size_t)s0 * 64 + c]);
        float4 va1 = __ldg(&ha4[(size_t)s1 * 64 + c]);
        float4 va2 = __ldg(&ha4[(size_t)s2 * 64 + c]);
        float4 va3 = __ldg(&ha4[(size_t)s3 * 64 + c]);
        float4 vb0 = __ldg(&hb4[(size_t)s0 * 64 + c]);
        float4 vb1 = __ldg(&hb4[(size_t)s1 * 64 + c]);
        float4 vb2 = __ldg(&hb4[(size_t)s2 * 64 + c]);
        float4 vb3 = __ldg(&hb4[(size_t)s3 * 64 + c]);
        ACC_EDGE(va0, vb0, w0);
        ACC_EDGE(va1, vb1, w1);
        ACC_EDGE(va2, vb2, w2);
        ACC_EDGE(va3, vb3, w3);
    }
    for (; i < end; i++) {
        int   s = __ldg(&csr_src[i]);
        float w = __ldg(&csr_w[i]);
        float4 va = __ldg(&ha4[(size_t)s * 64 + c]);
        float4 vb = __ldg(&hb4[(size_t)s * 64 + c]);
        ACC_EDGE(va, vb, w);
    }
#undef ACC_EDGE

    float4 ba = __ldg(&((const float4*)bias_a)[c]);
    float4 bb = __ldg(&((const float4*)bias_b)[c]);
    acca.x += ba.x; acca.y += ba.y; acca.z += ba.z; acca.w += ba.w;
    accb.x += bb.x; accb.y += bb.y; accb.z += bb.z; accb.w += bb.w;
    if (do_relu) {
        acca.x = fmaxf(acca.x, 0.f); acca.y = fmaxf(acca.y, 0.f);
        acca.z = fmaxf(acca.z, 0.f); acca.w = fmaxf(acca.w, 0.f);
        accb.x = fmaxf(accb.x, 0.f); accb.y = fmaxf(accb.y, 0.f);
        accb.z = fmaxf(accb.z, 0.f); accb.w = fmaxf(accb.w, 0.f);
    }

    const size_t off = (size_t)node * HDIM + 4 * c;
    float fa[4] = { acca.x, acca.y, acca.z, acca.w };
    float fb[4] = { accb.x, accb.y, accb.z, accb.w };
    __half hah[4], hal[4], hbh[4], hbl[4];
#pragma unroll
    for (int j = 0; j < 4; j++) {
        hah[j] = __float2half_rn(fa[j]);
        hal[j] = __float2half_rn(fa[j] - __half2float(hah[j]));
        hbh[j] = __float2half_rn(fb[j]);
        hbl[j] = __float2half_rn(fb[j] - __half2float(hbh[j]));
    }
    *(uint2*)(oa_hi + off) = *(uint2*)hah;
    *(uint2*)(oa_lo + off) = *(uint2*)hal;
    *(uint2*)(ob_hi + off) = *(uint2*)hbh;
    *(uint2*)(ob_lo + off) = *(uint2*)hbl;
}

// ============================================================================
// log_softmax variants (one warp per row)
// ============================================================================
__global__ void logsoftmax_split_kernel(const float* __restrict__ in,
                                        __half* __restrict__ out_hi,
                                        __half* __restrict__ out_lo,
                                        int nrows, int out_stride)
{
    const int L = HDIM;
    int row  = blockIdx.x * (blockDim.x >> 5) + (threadIdx.x >> 5);
    int lane = threadIdx.x & 31;
    if (row >= nrows) return;
    const float* r = in + (size_t)row * L;
    float vals[L / 32];
    float m = -3.4e38f;
#pragma unroll
    for (int t = 0; t < L / 32; t++) {
        vals[t] = r[lane + t * 32];
        m = fmaxf(m, vals[t]);
    }
#pragma unroll
    for (int o = 16; o; o >>= 1) m = fmaxf(m, __shfl_xor_sync(0xffffffffu, m, o));
    float s = 0.f;
#pragma unroll
    for (int t = 0; t < L / 32; t++) s += expf(vals[t] - m);
#pragma unroll
    for (int o = 16; o; o >>= 1) s += __shfl_xor_sync(0xffffffffu, s, o);
    float lse = m + logf(s);
    size_t base = (size_t)row * out_stride;
#pragma unroll
    for (int t = 0; t < L / 32; t++) {
        float v = vals[t] - lse;
        __half h = __float2half_rn(v);
        out_hi[base + lane + t * 32] = h;
        out_lo[base + lane + t * 32] = __float2half_rn(v - __half2float(h));
    }
}

template <int L>
__global__ void logsoftmax_kernel(const float* __restrict__ in, float* __restrict__ out,
                                  int nrows, int out_stride)
{
    int row  = blockIdx.x * (blockDim.x >> 5) + (threadIdx.x >> 5);
    int lane = threadIdx.x & 31;
    if (row >= nrows) return;
    const float* r = in + (size_t)row * L;
    float vals[L / 32];
    float m = -3.4e38f;
#pragma unroll
    for (int t = 0; t < L / 32; t++) {
        vals[t] = r[lane + t * 32];
        m = fmaxf(m, vals[t]);
    }
#pragma unroll
    for (int o = 16; o; o >>= 1) m = fmaxf(m, __shfl_xor_sync(0xffffffffu, m, o));
    float s = 0.f;
#pragma unroll
    for (int t = 0; t < L / 32; t++) s += expf(vals[t] - m);
#pragma unroll
    for (int o = 16; o; o >>= 1) s += __shfl_xor_sync(0xffffffffu, s, o);
    float lse = m + logf(s);
    float* wptr = out + (size_t)row * out_stride;
#pragma unroll
    for (int t = 0; t < L / 32; t++) wptr[lane + t * 32] = vals[t] - lse;
}

// ============================================================================
// host side
// ============================================================================
static void hgemm_pair(GemmArgs a0, GemmArgs a1, int M, int N, int K)
{
    dim3 grid((N + BN - 1) / BN, (M + BM - 1) / BM, 2);
    hgemm_kernel<<<grid, 256, SMEM_BYTES>>>(a0, a1, M, N, K);
}
static void hgemm_one(GemmArgs a, int M, int N, int K)
{
    dim3 grid((N + BN - 1) / BN, (M + BM - 1) / BM, 1);
    hgemm_kernel<<<grid, 256, SMEM_BYTES>>>(a, a, M, N, K);
}

static void split(const float* in, __half* hi, __half* lo, int n)
{
    int n4 = n / 4;
    split_kernel<<<(n4 + 255) / 256, 256>>>(in, hi, lo, n4);
}

extern "C" void kernel_launch(void* const* d_in, const int* in_sizes, int n_in,
                              void* d_out, int out_size)
{
    const float* x0   = (const float*)d_in[0];
    const float* x1   = (const float*)d_in[1];
    const int*   esrc = (const int*)d_in[2];
    const int*   edst = (const int*)d_in[3];
    const float* ew   = (const float*)d_in[4];
    const float* W1a = (const float*)d_in[5];  const float* b1a = (const float*)d_in[6];
    const float* W2a = (const float*)d_in[7];  const float* b2a = (const float*)d_in[8];
    const float* LWa = (const float*)d_in[9];  const float* Lba = (const float*)d_in[10];
    const float* W1b = (const float*)d_in[11]; const float* b1b = (const float*)d_in[12];
    const float* W2b = (const float*)d_in[13]; const float* b2b = (const float*)d_in[14];
    const float* LWb = (const float*)d_in[15]; const float* Lbb = (const float*)d_in[16];
    const float* LW  = (const float*)d_in[17]; const float* Lb  = (const float*)d_in[18];

    const int Nn = in_sizes[0] / F0DIM;
    const int E  = in_sizes[2];

    cudaFuncSetAttribute(hgemm_kernel,
                         cudaFuncAttributeMaxDynamicSharedMemorySize, SMEM_BYTES);

    float *Aa, *Ab;
    cudaGetSymbolAddress((void**)&Aa, g_Aa);
    cudaGetSymbolAddress((void**)&Ab, g_Ab);
    __half *X0hi, *X0lo, *X1hi, *X1lo, *Hahi, *Halo, *Hbhi, *Hblo, *CAThi, *CATlo, *Whi, *Wlo;
    cudaGetSymbolAddress((void**)&X0hi, g_X0hi);  cudaGetSymbolAddress((void**)&X0lo, g_X0lo);
    cudaGetSymbolAddress((void**)&X1hi, g_X1hi);  cudaGetSymbolAddress((void**)&X1lo, g_X1lo);
    cudaGetSymbolAddress((void**)&Hahi, g_Hahi);  cudaGetSymbolAddress((void**)&Halo, g_Halo);
    cudaGetSymbolAddress((void**)&Hbhi, g_Hbhi);  cudaGetSymbolAddress((void**)&Hblo, g_Hblo);
    cudaGetSymbolAddress((void**)&CAThi, g_CAThi); cudaGetSymbolAddress((void**)&CATlo, g_CATlo);
    cudaGetSymbolAddress((void**)&Whi, g_Whi);    cudaGetSymbolAddress((void**)&Wlo, g_Wlo);

    int *counts, *cursor, *rowptr, *csr_src;
    float *csr_w;
    cudaGetSymbolAddress((void**)&counts,  g_counts);
    cudaGetSymbolAddress((void**)&cursor,  g_cursor);
    cudaGetSymbolAddress((void**)&rowptr,  g_rowptr);
    cudaGetSymbolAddress((void**)&csr_src, g_csr_src);
    cudaGetSymbolAddress((void**)&csr_w,   g_csr_w);

    // ---- split inputs & weights to half planes ----
    split(x0, X0hi, X0lo, Nn * F0DIM);
    split(x1, X1hi, X1lo, Nn * F0DIM);
    split(W1a, Whi + OFF_W1a, Wlo + OFF_W1a, F0DIM * HDIM);
    split(W2a, Whi + OFF_W2a, Wlo + OFF_W2a, HDIM * HDIM);
    split(LWa, Whi + OFF_LWa, Wlo + OFF_LWa, HDIM * HDIM);
    split(W1b, Whi + OFF_W1b, Wlo + OFF_W1b, F0DIM * HDIM);
    split(W2b, Whi + OFF_W2b, Wlo + OFF_W2b, HDIM * HDIM);
    split(LWb, Whi + OFF_LWb, Wlo + OFF_LWb, HDIM * HDIM);
    split(LW,  Whi + OFF_LW,  Wlo + OFF_LW,  2 * HDIM * CDIM);

    // ---- build CSR by dst ----
    cudaMemsetAsync(counts, 0, Nn * sizeof(int), 0);
    cudaMemsetAsync(cursor, 0, Nn * sizeof(int), 0);
    count_kernel<<<(E + 255) / 256, 256>>>(edst, counts, E);
    scan_kernel<<<1, 1024>>>(counts, rowptr, Nn);
    scatter_kernel<<<(E + 255) / 256, 256>>>(esrc, edst, ew, rowptr, cursor,
                                             csr_src, csr_w, E);

    const int spmmGrid = (Nn + 3) / 4;

    // ---- layer 1 (both branches in one launch) ----
    hgemm_pair({ X0hi, X0lo, Whi + OFF_W1a, Wlo + OFF_W1a, nullptr, Aa },
               { X1hi, X1lo, Whi + OFF_W1b, Wlo + OFF_W1b, nullptr, Ab },
               Nn, HDIM, F0DIM);
    spmm_csr_dual_kernel<<<spmmGrid, 256>>>(rowptr, csr_src, csr_w, Aa, Ab,
                                            Hahi, Halo, Hbhi, Hblo, b1a, b1b, Nn, 1);
    // ---- layer 2 ----
    hgemm_pair({ Hahi, Halo, Whi + OFF_W2a, Wlo + OFF_W2a, nullptr, Aa },
               { Hbhi, Hblo, Whi + OFF_W2b, Wlo + OFF_W2b, nullptr, Ab },
               Nn, HDIM, HDIM);
    spmm_csr_dual_kernel<<<spmmGrid, 256>>>(rowptr, csr_src, csr_w, Aa, Ab,
                                            Hahi, Halo, Hbhi, Hblo, b2a, b2b, Nn, 0);
    // ---- branch heads ----
    hgemm_pair({ Hahi, Halo, Whi + OFF_LWa, Wlo + OFF_LWa, Lba, Aa },
               { Hbhi, Hblo, Whi + OFF_LWb, Wlo + OFF_LWb, Lbb, Ab },
               Nn, HDIM, HDIM);
    logsoftmax_split_kernel<<<(Nn + 7) / 8, 256>>>(Aa, CAThi,        CATlo,        Nn, 2 * HDIM);
    logsoftmax_split_kernel<<<(Nn + 7) / 8, 256>>>(Ab, CAThi + HDIM, CATlo + HDIM, Nn, 2 * HDIM);

    // ---- final: out = log_softmax(CAT @ LW + Lb) ----
    hgemm_one({ CAThi, CATlo, Whi + OFF_LW, Wlo + OFF_LW, Lb, Aa }, Nn, CDIM, 2 * HDIM);
    logsoftmax_kernel<CDIM><<<(Nn + 7) / 8, 256>>>(Aa, (float*)d_out, Nn, CDIM);
}

// round 10
// speedup vs baseline: 1.1664x; 1.0706x over previous
#include <cuda_runtime.h>
#include <cuda_fp16.h>
#include <math.h>
#include <stdint.h>

#define HDIM   256
#define F0DIM  512
#define CDIM   64
#define MAXN   50000
#define MAXE   800000

// -------- static device scratch (no allocations allowed) --------
__device__ float g_Aa[(size_t)MAXN * HDIM];
__device__ float g_Ab[(size_t)MAXN * HDIM];

__device__ __align__(256) __half g_X0hi[(size_t)MAXN * F0DIM];
__device__ __align__(256) __half g_X0lo[(size_t)MAXN * F0DIM];
__device__ __align__(256) __half g_X1hi[(size_t)MAXN * F0DIM];
__device__ __align__(256) __half g_X1lo[(size_t)MAXN * F0DIM];
__device__ __align__(256) __half g_Hahi[(size_t)MAXN * HDIM];
__device__ __align__(256) __half g_Halo[(size_t)MAXN * HDIM];
__device__ __align__(256) __half g_Hbhi[(size_t)MAXN * HDIM];
__device__ __align__(256) __half g_Hblo[(size_t)MAXN * HDIM];
__device__ __align__(256) __half g_CAThi[(size_t)MAXN * 2 * HDIM];
__device__ __align__(256) __half g_CATlo[(size_t)MAXN * 2 * HDIM];
__device__ __align__(256) __half g_Whi[557056];
__device__ __align__(256) __half g_Wlo[557056];

__device__ int   g_counts[MAXN];
__device__ int   g_cursor[MAXN];
__device__ int   g_rowptr[MAXN + 1];
__device__ int   g_csr_src[MAXE];
__device__ float g_csr_w[MAXE];

// weight plane offsets
#define OFF_W1a 0
#define OFF_W2a 131072
#define OFF_LWa 196608
#define OFF_W1b 262144
#define OFF_W2b 393216
#define OFF_LWb 458752
#define OFF_LW  524288

// ============================================================================
// batched fp32 -> (hi, lo) half-plane splits
// ============================================================================
__device__ __forceinline__ void split4_store(const float* in, __half* hi, __half* lo,
                                             size_t i4)
{
    float4 v = __ldg(((const float4*)in) + i4);
    float f[4] = { v.x, v.y, v.z, v.w };
    __half h[4], l[4];
#pragma unroll
    for (int j = 0; j < 4; j++) {
        h[j] = __float2half_rn(f[j]);
        l[j] = __float2half_rn(f[j] - __half2float(h[j]));
    }
    *(uint2*)(hi + 4 * i4) = *(uint2*)h;
    *(uint2*)(lo + 4 * i4) = *(uint2*)l;
}

// two big inputs in one launch (blockIdx.z selects)
__global__ void split_x_kernel(const float* __restrict__ x0, __half* __restrict__ h0,
                               __half* __restrict__ l0,
                               const float* __restrict__ x1, __half* __restrict__ h1,
                               __half* __restrict__ l1, int n4)
{
    int i = blockIdx.x * blockDim.x + threadIdx.x;
    if (i >= n4) return;
    if (blockIdx.z == 0) split4_store(x0, h0, l0, i);
    else                 split4_store(x1, h1, l1, i);
}

struct WSplit { const float* src; int off; int n4; };
struct WSplit7 { WSplit d[7]; };

__global__ void split_w_kernel(WSplit7 ws, __half* __restrict__ hi, __half* __restrict__ lo)
{
    const WSplit& d = ws.d[blockIdx.y];
    int i = blockIdx.x * blockDim.x + threadIdx.x;
    if (i >= d.n4) return;
    split4_store(d.src, hi + d.off, lo + d.off, i);
}

// ============================================================================
// fp16 TC GEMM (256 thr, 8 warps 2x4, warp tile 64x32), pre-split hi/lo
// planes, 128x128x32 tile, double-buffered SMEM. blockIdx.z selects branch.
// ============================================================================
#define BM 128
#define BN 128
#define BKK 32
#define NK2 16
#define SA2 136
#define SB2 136
#define APLANE (NK2 * SA2)
#define BPLANE (NK2 * SB2)
#define BUF_H2 (2 * APLANE + 2 * BPLANE)
#define SMEM_BYTES (2 * BUF_H2 * 4)

__device__ __forceinline__ void mma_f16(float c[4], const uint32_t a[4], const uint32_t b[2]) {
    asm volatile(
        "mma.sync.aligned.m16n8k16.row.col.f32.f16.f16.f32 "
        "{%0,%1,%2,%3}, {%4,%5,%6,%7}, {%8,%9}, {%0,%1,%2,%3};"
        : "+f"(c[0]), "+f"(c[1]), "+f"(c[2]), "+f"(c[3])
        : "r"(a[0]), "r"(a[1]), "r"(a[2]), "r"(a[3]), "r"(b[0]), "r"(b[1]));
}

struct GemmArgs {
    const __half* Ahi; const __half* Alo;
    const __half* Bhi; const __half* Blo;
    const float*  bias; float* C;
};

__global__ void __launch_bounds__(256)
hgemm_kernel(GemmArgs a0, GemmArgs a1, int M, int N, int K)
{
    extern __shared__ __half2 sm[];

    const GemmArgs& A = blockIdx.z ? a1 : a0;
    const __half* __restrict__ Ahi = A.Ahi;
    const __half* __restrict__ Alo = A.Alo;
    const __half* __restrict__ Bhi = A.Bhi;
    const __half* __restrict__ Blo = A.Blo;
    const float*  __restrict__ bias = A.bias;
    float* __restrict__ C = A.C;

    const int tid  = threadIdx.x;
    const int warp = tid >> 5;
    const int lane = tid & 31;
    const int g    = lane >> 2;
    const int tig  = lane & 3;
    const int mBase = (warp & 1) * 64;
    const int nBase = (warp >> 1) * 32;
    const int rowBase = blockIdx.y * BM;
    const int colBase = blockIdx.x * BN;

    float acc[4][4][4];
#pragma unroll
    for (int i = 0; i < 4; i++)
#pragma unroll
        for (int j = 0; j < 4; j++)
#pragma unroll
            for (int r = 0; r < 4; r++) acc[i][j][r] = 0.f;

    const int ar   = tid & 127;
    const int ak2  = (tid >> 7) * 8;
    const int aKh  = ak2 * 2;
    const int bcol0 = 2 * lane;

    uint4    pa[4];
    uint32_t pbr[16];

    auto loadG = [&](int k0) {
        const int grow = rowBase + ar;
        if (grow < M) {
            const __half* pH = Ahi + (size_t)grow * K + k0 + aKh;
            const __half* pL = Alo + (size_t)grow * K + k0 + aKh;
            pa[0] = *(const uint4*)pH;       pa[1] = *(const uint4*)(pH + 8);
            pa[2] = *(const uint4*)pL;       pa[3] = *(const uint4*)(pL + 8);
        } else {
            uint4 z = make_uint4(0u, 0u, 0u, 0u);
            pa[0] = z; pa[1] = z; pa[2] = z; pa[3] = z;
        }
#pragma unroll
        for (int s = 0; s < 2; s++) {
            const int k2 = warp + 8 * s;
            const int kk = k0 + 2 * k2;
#pragma unroll
            for (int c = 0; c < 2; c++) {
                const int col = colBase + bcol0 + 64 * c;
                const bool ok = (col < N);
                const __half* q = Bhi + (size_t)kk * N + col;
                const __half* r = Blo + (size_t)kk * N + col;
                pbr[((0 * 2 + s) * 2 + 0) * 2 + c] = ok ? *(const uint32_t*)q       : 0u;
                pbr[((0 * 2 + s) * 2 + 1) * 2 + c] = ok ? *(const uint32_t*)(q + N) : 0u;
                pbr[((1 * 2 + s) * 2 + 0) * 2 + c] = ok ? *(const uint32_t*)r       : 0u;
                pbr[((1 * 2 + s) * 2 + 1) * 2 + c] = ok ? *(const uint32_t*)(r + N) : 0u;
            }
        }
    };

    auto storeS = [&](int buf) {
        __half2* sA_hi = sm + (size_t)buf * BUF_H2;
        __half2* sA_lo = sA_hi + APLANE;
        __half2* sB_hi = sA_lo + APLANE;
        __half2* sB_lo = sB_hi + BPLANE;
#pragma unroll
        for (int pl = 0; pl < 2; pl++) {
            __half2* dst = pl ? sA_lo : sA_hi;
#pragma unroll
            for (int j = 0; j < 2; j++) {
                uint4 v = pa[pl * 2 + j];
                const uint32_t u[4] = { v.x, v.y, v.z, v.w };
#pragma unroll
                for (int q = 0; q < 4; q++)
                    dst[(ak2 + j * 4 + q) * SA2 + ar] = *(const __half2*)&u[q];
            }
        }
#pragma unroll
        for (int pl = 0; pl < 2; pl++) {
            __half2* dst = pl ? sB_lo : sB_hi;
#pragma unroll
            for (int s = 0; s < 2; s++) {
                const int k2 = warp + 8 * s;
#pragma unroll
                for (int c = 0; c < 2; c++) {
                    uint32_t r0 = pbr[((pl * 2 + s) * 2 + 0) * 2 + c];
                    uint32_t r1 = pbr[((pl * 2 + s) * 2 + 1) * 2 + c];
                    uint2 st = make_uint2(__byte_perm(r0, r1, 0x5410),
                                          __byte_perm(r0, r1, 0x7632));
                    *(uint2*)&dst[k2 * SB2 + bcol0 + 64 * c] = st;
                }
            }
        }
    };

    const int nIter = K / BKK;
    loadG(0);
    storeS(0);
    __syncthreads();
    if (nIter > 1) loadG(BKK);

    for (int it = 0; it < nIter; it++) {
        const __half2* sA_hi = sm + (size_t)(it & 1) * BUF_H2;
        const __half2* sA_lo = sA_hi + APLANE;
        const __half2* sB_hi = sA_lo + APLANE;
        const __half2* sB_lo = sB_hi + BPLANE;

#pragma unroll
        for (int ks = 0; ks < 2; ks++) {
            const int k2a = ks * 8 + tig;
            const int k2b = k2a + 4;

            uint32_t ahi[4][4], alo[4][4];
#pragma unroll
            for (int mi = 0; mi < 4; mi++) {
                const int m0 = mBase + mi * 16 + g;
                ahi[mi][0] = *(const uint32_t*)&sA_hi[k2a * SA2 + m0];
                ahi[mi][1] = *(const uint32_t*)&sA_hi[k2a * SA2 + m0 + 8];
                ahi[mi][2] = *(const uint32_t*)&sA_hi[k2b * SA2 + m0];
                ahi[mi][3] = *(const uint32_t*)&sA_hi[k2b * SA2 + m0 + 8];
                alo[mi][0] = *(const uint32_t*)&sA_lo[k2a * SA2 + m0];
                alo[mi][1] = *(const uint32_t*)&sA_lo[k2a * SA2 + m0 + 8];
                alo[mi][2] = *(const uint32_t*)&sA_lo[k2b * SA2 + m0];
                alo[mi][3] = *(const uint32_t*)&sA_lo[k2b * SA2 + m0 + 8];
            }
            uint32_t bhi[4][2], blo[4][2];
#pragma unroll
            for (int ni = 0; ni < 4; ni++) {
                const int n0 = nBase + ni * 8 + g;
                bhi[ni][0] = *(const uint32_t*)&sB_hi[k2a * SB2 + n0];
                bhi[ni][1] = *(const uint32_t*)&sB_hi[k2b * SB2 + n0];
                blo[ni][0] = *(const uint32_t*)&sB_lo[k2a * SB2 + n0];
                blo[ni][1] = *(const uint32_t*)&sB_lo[k2b * SB2 + n0];
            }
#pragma unroll
            for (int mi = 0; mi < 4; mi++)
#pragma unroll
                for (int ni = 0; ni < 4; ni++)
                    mma_f16(acc[mi][ni], alo[mi], bhi[ni]);
#pragma unroll
            for (int mi = 0; mi < 4; mi++)
#pragma unroll
                for (int ni = 0; ni < 4; ni++)
                    mma_f16(acc[mi][ni], ahi[mi], blo[ni]);
#pragma unroll
            for (int mi = 0; mi < 4; mi++)
#pragma unroll
                for (int ni = 0; ni < 4; ni++)
                    mma_f16(acc[mi][ni], ahi[mi], bhi[ni]);
        }

        if (it + 1 < nIter) storeS((it + 1) & 1);
        __syncthreads();
        if (it + 2 < nIter) loadG((it + 2) * BKK);
    }

#pragma unroll
    for (int mi = 0; mi < 4; mi++) {
#pragma unroll
        for (int ni = 0; ni < 4; ni++) {
            const int col = colBase + nBase + ni * 8 + 2 * tig;
            if (col >= N) continue;
            float bx = 0.f, by = 0.f;
            if (bias) { bx = __ldg(&bias[col]); by = __ldg(&bias[col + 1]); }
            const int row0 = rowBase + mBase + mi * 16 + g;
            const int row1 = row0 + 8;
            if (row0 < M) {
                float2 v = make_float2(acc[mi][ni][0] + bx, acc[mi][ni][1] + by);
                *(float2*)(C + (size_t)row0 * N + col) = v;
            }
            if (row1 < M) {
                float2 v = make_float2(acc[mi][ni][2] + bx, acc[mi][ni][3] + by);
                *(float2*)(C + (size_t)row1 * N + col) = v;
            }
        }
    }
}

// ============================================================================
// CSR build: histogram -> scan -> scatter
// ============================================================================
__global__ void count_kernel(const int* __restrict__ dst, int* __restrict__ counts, int E)
{
    int e = blockIdx.x * blockDim.x + threadIdx.x;
    if (e < E) atomicAdd(&counts[dst[e]], 1);
}

__global__ void __launch_bounds__(1024)
scan_kernel(const int* __restrict__ counts, int* __restrict__ rowptr, int n)
{
    __shared__ int sm[1024];
    __shared__ int carry_s;
    int tid = threadIdx.x;
    if (tid == 0) carry_s = 0;
    __syncthreads();
    for (int base = 0; base < n; base += 1024) {
        int v = (base + tid < n) ? counts[base + tid] : 0;
        sm[tid] = v;
        __syncthreads();
#pragma unroll
        for (int off = 1; off < 1024; off <<= 1) {
            int t = (tid >= off) ? sm[tid - off] : 0;
            __syncthreads();
            sm[tid] += t;
            __syncthreads();
        }
        int carry = carry_s;
        if (base + tid < n) rowptr[base + tid] = carry + sm[tid] - v;
        __syncthreads();
        if (tid == 1023) carry_s = carry + sm[1023];
        __syncthreads();
    }
    if (tid == 0) rowptr[n] = carry_s;
}

__global__ void scatter_kernel(const int* __restrict__ src, const int* __restrict__ dst,
                               const float* __restrict__ w,
                               const int* __restrict__ rowptr, int* __restrict__ cursor,
                               int* __restrict__ csr_src, float* __restrict__ csr_w, int E)
{
    int e = blockIdx.x * blockDim.x + threadIdx.x;
    if (e >= E) return;
    int d = dst[e];
    int pos = rowptr[d] + atomicAdd(&cursor[d], 1);
    csr_src[pos] = src[e];
    csr_w[pos]   = w[e];
}

// ============================================================================
// Gather SpMM, dual branch, bias(+relu) fused, 4-edge unrolled,
// emits hi/lo half planes.
// ============================================================================
__global__ void __launch_bounds__(256)
spmm_csr_dual_kernel(const int* __restrict__ rowptr,
                     const int* __restrict__ csr_src, const float* __restrict__ csr_w,
                     const float* __restrict__ ha, const float* __restrict__ hb,
                     __half* __restrict__ oa_hi, __half* __restrict__ oa_lo,
                     __half* __restrict__ ob_hi, __half* __restrict__ ob_lo,
                     const float* __restrict__ bias_a, const float* __restrict__ bias_b,
                     int Nn, int do_relu)
{
    int node = blockIdx.x * 4 + (threadIdx.x >> 6);
    int c    = threadIdx.x & 63;
    if (node >= Nn) return;

    const float4* ha4 = (const float4*)ha;
    const float4* hb4 = (const float4*)hb;

    float4 acca = make_float4(0.f, 0.f, 0.f, 0.f);
    float4 accb = make_float4(0.f, 0.f, 0.f, 0.f);

    const int beg = __ldg(&rowptr[node]);
    const int end = __ldg(&rowptr[node + 1]);
    int i = beg;

#define ACC_EDGE(va, vb, wv)                                            \
    do {                                                                \
        acca.x = fmaf(wv, va.x, acca.x); acca.y = fmaf(wv, va.y, acca.y);\
        acca.z = fmaf(wv, va.z, acca.z); acca.w = fmaf(wv, va.w, acca.w);\
        accb.x = fmaf(wv, vb.x, accb.x); accb.y = fmaf(wv, vb.y, accb.y);\
        accb.z = fmaf(wv, vb.z, accb.z); accb.w = fmaf(wv, vb.w, accb.w);\
    } while (0)

    for (; i + 4 <= end; i += 4) {
        int   s0 = __ldg(&csr_src[i]),     s1 = __ldg(&csr_src[i + 1]);
        int   s2 = __ldg(&csr_src[i + 2]), s3 = __ldg(&csr_src[i + 3]);
        float w0 = __ldg(&csr_w[i]),       w1 = __ldg(&csr_w[i + 1]);
        float w2 = __ldg(&csr_w[i + 2]),   w3 = __ldg(&csr_w[i + 3]);
        float4 va0 = __ldg(&ha4[(size_t)s0 * 64 + c]);
        float4 va1 = __ldg(&ha4[(size_t)s1 * 64 + c]);
        float4 va2 = __ldg(&ha4[(size_t)s2 * 64 + c]);
        float4 va3 = __ldg(&ha4[(size_t)s3 * 64 + c]);
        float4 vb0 = __ldg(&hb4[(size_t)s0 * 64 + c]);
        float4 vb1 = __ldg(&hb4[(size_t)s1 * 64 + c]);
        float4 vb2 = __ldg(&hb4[(size_t)s2 * 64 + c]);
        float4 vb3 = __ldg(&hb4[(size_t)s3 * 64 + c]);
        ACC_EDGE(va0, vb0, w0);
        ACC_EDGE(va1, vb1, w1);
        ACC_EDGE(va2, vb2, w2);
        ACC_EDGE(va3, vb3, w3);
    }
    for (; i < end; i++) {
        int   s = __ldg(&csr_src[i]);
        float w = __ldg(&csr_w[i]);
        float4 va = __ldg(&ha4[(size_t)s * 64 + c]);
        float4 vb = __ldg(&hb4[(size_t)s * 64 + c]);
        ACC_EDGE(va, vb, w);
    }
#undef ACC_EDGE

    float4 ba = __ldg(&((const float4*)bias_a)[c]);
    float4 bb = __ldg(&((const float4*)bias_b)[c]);
    acca.x += ba.x; acca.y += ba.y; acca.z += ba.z; acca.w += ba.w;
    accb.x += bb.x; accb.y += bb.y; accb.z += bb.z; accb.w += bb.w;
    if (do_relu) {
        acca.x = fmaxf(acca.x, 0.f); acca.y = fmaxf(acca.y, 0.f);
        acca.z = fmaxf(acca.z, 0.f); acca.w = fmaxf(acca.w, 0.f);
        accb.x = fmaxf(accb.x, 0.f); accb.y = fmaxf(accb.y, 0.f);
        accb.z = fmaxf(accb.z, 0.f); accb.w = fmaxf(accb.w, 0.f);
    }

    const size_t off = (size_t)node * HDIM + 4 * c;
    float fa[4] = { acca.x, acca.y, acca.z, acca.w };
    float fb[4] = { accb.x, accb.y, accb.z, accb.w };
    __half hah[4], hal[4], hbh[4], hbl[4];
#pragma unroll
    for (int j = 0; j < 4; j++) {
        hah[j] = __float2half_rn(fa[j]);
        hal[j] = __float2half_rn(fa[j] - __half2float(hah[j]));
        hbh[j] = __float2half_rn(fb[j]);
        hbl[j] = __float2half_rn(fb[j] - __half2float(hbh[j]));
    }
    *(uint2*)(oa_hi + off) = *(uint2*)hah;
    *(uint2*)(oa_lo + off) = *(uint2*)hal;
    *(uint2*)(ob_hi + off) = *(uint2*)hbh;
    *(uint2*)(ob_lo + off) = *(uint2*)hbl;
}

// ============================================================================
// log_softmax variants
// ============================================================================
// batched: blockIdx.y selects branch (in0->out base, in1->out base+HDIM)
__global__ void logsoftmax_split2_kernel(const float* __restrict__ in0,
                                         const float* __restrict__ in1,
                                         __half* __restrict__ out_hi,
                                         __half* __restrict__ out_lo,
                                         int nrows, int out_stride)
{
    const int L = HDIM;
    int row  = blockIdx.x * (blockDim.x >> 5) + (threadIdx.x >> 5);
    int lane = threadIdx.x & 31;
    if (row >= nrows) return;
    const float* in = blockIdx.y ? in1 : in0;
    const int obase = blockIdx.y ? HDIM : 0;
    const float* r = in + (size_t)row * L;
    float vals[L / 32];
    float m = -3.4e38f;
#pragma unroll
    for (int t = 0; t < L / 32; t++) {
        vals[t] = r[lane + t * 32];
        m = fmaxf(m, vals[t]);
    }
#pragma unroll
    for (int o = 16; o; o >>= 1) m = fmaxf(m, __shfl_xor_sync(0xffffffffu, m, o));
    float s = 0.f;
#pragma unroll
    for (int t = 0; t < L / 32; t++) s += expf(vals[t] - m);
#pragma unroll
    for (int o = 16; o; o >>= 1) s += __shfl_xor_sync(0xffffffffu, s, o);
    float lse = m + logf(s);
    size_t base = (size_t)row * out_stride + obase;
#pragma unroll
    for (int t = 0; t < L / 32; t++) {
        float v = vals[t] - lse;
        __half h = __float2half_rn(v);
        out_hi[base + lane + t * 32] = h;
        out_lo[base + lane + t * 32] = __float2half_rn(v - __half2float(h));
    }
}

template <int L>
__global__ void logsoftmax_kernel(const float* __restrict__ in, float* __restrict__ out,
                                  int nrows, int out_stride)
{
    int row  = blockIdx.x * (blockDim.x >> 5) + (threadIdx.x >> 5);
    int lane = threadIdx.x & 31;
    if (row >= nrows) return;
    const float* r = in + (size_t)row * L;
    float vals[L / 32];
    float m = -3.4e38f;
#pragma unroll
    for (int t = 0; t < L / 32; t++) {
        vals[t] = r[lane + t * 32];
        m = fmaxf(m, vals[t]);
    }
#pragma unroll
    for (int o = 16; o; o >>= 1) m = fmaxf(m, __shfl_xor_sync(0xffffffffu, m, o));
    float s = 0.f;
#pragma unroll
    for (int t = 0; t < L / 32; t++) s += expf(vals[t] - m);
#pragma unroll
    for (int o = 16; o; o >>= 1) s += __shfl_xor_sync(0xffffffffu, s, o);
    float lse = m + logf(s);
    float* wptr = out + (size_t)row * out_stride;
#pragma unroll
    for (int t = 0; t < L / 32; t++) wptr[lane + t * 32] = vals[t] - lse;
}

// ============================================================================
// host side
// ============================================================================
static void hgemm_pair(GemmArgs a0, GemmArgs a1, int M, int N, int K)
{
    dim3 grid((N + BN - 1) / BN, (M + BM - 1) / BM, 2);
    hgemm_kernel<<<grid, 256, SMEM_BYTES>>>(a0, a1, M, N, K);
}
static void hgemm_one(GemmArgs a, int M, int N, int K)
{
    dim3 grid((N + BN - 1) / BN, (M + BM - 1) / BM, 1);
    hgemm_kernel<<<grid, 256, SMEM_BYTES>>>(a, a, M, N, K);
}

extern "C" void kernel_launch(void* const* d_in, const int* in_sizes, int n_in,
                              void* d_out, int out_size)
{
    const float* x0   = (const float*)d_in[0];
    const float* x1   = (const float*)d_in[1];
    const int*   esrc = (const int*)d_in[2];
    const int*   edst = (const int*)d_in[3];
    const float* ew   = (const float*)d_in[4];
    const float* W1a = (const float*)d_in[5];  const float* b1a = (const float*)d_in[6];
    const float* W2a = (const float*)d_in[7];  const float* b2a = (const float*)d_in[8];
    const float* LWa = (const float*)d_in[9];  const float* Lba = (const float*)d_in[10];
    const float* W1b = (const float*)d_in[11]; const float* b1b = (const float*)d_in[12];
    const float* W2b = (const float*)d_in[13]; const float* b2b = (const float*)d_in[14];
    const float* LWb = (const float*)d_in[15]; const float* Lbb = (const float*)d_in[16];
    const float* LW  = (const float*)d_in[17]; const float* Lb  = (const float*)d_in[18];

    const int Nn = in_sizes[0] / F0DIM;
    const int E  = in_sizes[2];

    // one-time host-side setup (first call is the uncaptured correctness run)
    static cudaStream_t s1 = nullptr;
    static cudaEvent_t evFork = nullptr, evJoin = nullptr;
    if (!s1) {
        cudaFuncSetAttribute(hgemm_kernel,
                             cudaFuncAttributeMaxDynamicSharedMemorySize, SMEM_BYTES);
        cudaStreamCreateWithFlags(&s1, cudaStreamNonBlocking);
        cudaEventCreateWithFlags(&evFork, cudaEventDisableTiming);
        cudaEventCreateWithFlags(&evJoin, cudaEventDisableTiming);
    }

    float *Aa, *Ab;
    cudaGetSymbolAddress((void**)&Aa, g_Aa);
    cudaGetSymbolAddress((void**)&Ab, g_Ab);
    __half *X0hi, *X0lo, *X1hi, *X1lo, *Hahi, *Halo, *Hbhi, *Hblo, *CAThi, *CATlo, *Whi, *Wlo;
    cudaGetSymbolAddress((void**)&X0hi, g_X0hi);  cudaGetSymbolAddress((void**)&X0lo, g_X0lo);
    cudaGetSymbolAddress((void**)&X1hi, g_X1hi);  cudaGetSymbolAddress((void**)&X1lo, g_X1lo);
    cudaGetSymbolAddress((void**)&Hahi, g_Hahi);  cudaGetSymbolAddress((void**)&Halo, g_Halo);
    cudaGetSymbolAddress((void**)&Hbhi, g_Hbhi);  cudaGetSymbolAddress((void**)&Hblo, g_Hblo);
    cudaGetSymbolAddress((void**)&CAThi, g_CAThi); cudaGetSymbolAddress((void**)&CATlo, g_CATlo);
    cudaGetSymbolAddress((void**)&Whi, g_Whi);    cudaGetSymbolAddress((void**)&Wlo, g_Wlo);

    int *counts, *cursor, *rowptr, *csr_src;
    float *csr_w;
    cudaGetSymbolAddress((void**)&counts,  g_counts);
    cudaGetSymbolAddress((void**)&cursor,  g_cursor);
    cudaGetSymbolAddress((void**)&rowptr,  g_rowptr);
    cudaGetSymbolAddress((void**)&csr_src, g_csr_src);
    cudaGetSymbolAddress((void**)&csr_w,   g_csr_w);

    // ---- fork: CSR build on side stream, overlapped with splits + layer-1 ----
    cudaEventRecord(evFork, 0);
    cudaStreamWaitEvent(s1, evFork, 0);
    cudaMemsetAsync(counts, 0, Nn * sizeof(int), s1);
    cudaMemsetAsync(cursor, 0, Nn * sizeof(int), s1);
    count_kernel<<<(E + 255) / 256, 256, 0, s1>>>(edst, counts, E);
    scan_kernel<<<1, 1024, 0, s1>>>(counts, rowptr, Nn);
    scatter_kernel<<<(E + 255) / 256, 256, 0, s1>>>(esrc, edst, ew, rowptr, cursor,
                                                    csr_src, csr_w, E);
    cudaEventRecord(evJoin, s1);

    // ---- main stream: batched splits ----
    {
        int n4 = Nn * F0DIM / 4;
        dim3 grid((n4 + 255) / 256, 1, 2);
        split_x_kernel<<<grid, 256>>>(x0, X0hi, X0lo, x1, X1hi, X1lo, n4);
    }
    {
        WSplit7 ws = {{
            { W1a, OFF_W1a, F0DIM * HDIM / 4 },
            { W2a, OFF_W2a, HDIM * HDIM / 4 },
            { LWa, OFF_LWa, HDIM * HDIM / 4 },
            { W1b, OFF_W1b, F0DIM * HDIM / 4 },
            { W2b, OFF_W2b, HDIM * HDIM / 4 },
            { LWb, OFF_LWb, HDIM * HDIM / 4 },
            { LW,  OFF_LW,  2 * HDIM * CDIM / 4 },
        }};
        dim3 grid((F0DIM * HDIM / 4 + 255) / 256, 7);
        split_w_kernel<<<grid, 256>>>(ws, Whi, Wlo);
    }

    const int spmmGrid = (Nn + 3) / 4;

    // ---- layer 1 (both branches in one launch) ----
    hgemm_pair({ X0hi, X0lo, Whi + OFF_W1a, Wlo + OFF_W1a, nullptr, Aa },
               { X1hi, X1lo, Whi + OFF_W1b, Wlo + OFF_W1b, nullptr, Ab },
               Nn, HDIM, F0DIM);
    // join CSR before first spmm
    cudaStreamWaitEvent(0, evJoin, 0);
    spmm_csr_dual_kernel<<<spmmGrid, 256>>>(rowptr, csr_src, csr_w, Aa, Ab,
                                            Hahi, Halo, Hbhi, Hblo, b1a, b1b, Nn, 1);
    // ---- layer 2 ----
    hgemm_pair({ Hahi, Halo, Whi + OFF_W2a, Wlo + OFF_W2a, nullptr, Aa },
               { Hbhi, Hblo, Whi + OFF_W2b, Wlo + OFF_W2b, nullptr, Ab },
               Nn, HDIM, HDIM);
    spmm_csr_dual_kernel<<<spmmGrid, 256>>>(rowptr, csr_src, csr_w, Aa, Ab,
                                            Hahi, Halo, Hbhi, Hblo, b2a, b2b, Nn, 0);
    // ---- branch heads ----
    hgemm_pair({ Hahi, Halo, Whi + OFF_LWa, Wlo + OFF_LWa, Lba, Aa },
               { Hbhi, Hblo, Whi + OFF_LWb, Wlo + OFF_LWb, Lbb, Ab },
               Nn, HDIM, HDIM);
    {
        dim3 grid((Nn + 7) / 8, 2);
        logsoftmax_split2_kernel<<<grid, 256>>>(Aa, Ab, CAThi, CATlo, Nn, 2 * HDIM);
    }

    // ---- final: out = log_softmax(CAT @ LW + Lb) ----
    hgemm_one({ CAThi, CATlo, Whi + OFF_LW, Wlo + OFF_LW, Lb, Aa }, Nn, CDIM, 2 * HDIM);
    logsoftmax_kernel<CDIM><<<(Nn + 7) / 8, 256>>>(Aa, (float*)d_out, Nn, CDIM);
}